// round 1
// baseline (speedup 1.0000x reference)
#include <cuda_runtime.h>

#define FMAXV 3.4028235e38f
#define APER 256

// Scratch (allocation-free: static device globals)
__device__ float g_K[4096 * 1024];
__device__ float g_Q[4096 * 1024];
__device__ float g_V[4096 * 1024];
__device__ float g_Y[4096 * 1024];

// Classic 128x128 tile SGEMM, K-tile 8, 256 threads, 8x8 per thread.
// TA=0: A is [M,Kd] row-major (lda=Kd). TA=1: A is [Kd,M], read A[k][i] (lda=M).
// TB=0: B is [Kd,N] row-major (ldb=N). TB=1: B is [N,Kd], read B[j][k] (ldb=Kd).
// MASK: epilogue applies aperture mask (C[i][j] = -FMAX unless j - i > APER),
//       and fully-masked 128x128 blocks skip the GEMM entirely.
template <int TA, int TB, bool MASK>
__global__ void __launch_bounds__(256)
sgemm_kernel(const float* __restrict__ A, const float* __restrict__ B,
             float* __restrict__ C, int M, int N, int Kd,
             int lda, int ldb, int ldc, float alpha)
{
    __shared__ float As[8][128];
    __shared__ float Bs[8][128];

    const int tid = threadIdx.x;
    const int jb = blockIdx.x * 128;
    const int ib = blockIdx.y * 128;
    const int tx = tid & 15;
    const int ty = tid >> 4;
    const int r0 = ty * 8;
    const int c0 = tx * 8;

    if (MASK && (jb + 127 - ib <= APER)) {
        // whole tile masked: write -FMAX, no GEMM
        #pragma unroll
        for (int r = 0; r < 8; r++) {
            #pragma unroll
            for (int c = 0; c < 8; c++) {
                C[(size_t)(ib + r0 + r) * ldc + (jb + c0 + c)] = -FMAXV;
            }
        }
        return;
    }

    float acc[8][8];
    #pragma unroll
    for (int r = 0; r < 8; r++)
        #pragma unroll
        for (int c = 0; c < 8; c++) acc[r][c] = 0.f;

    for (int k0 = 0; k0 < Kd; k0 += 8) {
        // ---- load A tile into As[kk][row] ----
        if (TA == 0) {
            int row  = tid >> 1;
            int kofs = (tid & 1) * 4;
            float4 v = *(const float4*)&A[(size_t)(ib + row) * lda + k0 + kofs];
            As[kofs + 0][row] = v.x;
            As[kofs + 1][row] = v.y;
            As[kofs + 2][row] = v.z;
            As[kofs + 3][row] = v.w;
        } else {
            int kk = tid >> 5;
            int c4 = (tid & 31) * 4;
            float4 v = *(const float4*)&A[(size_t)(k0 + kk) * lda + ib + c4];
            *(float4*)&As[kk][c4] = v;
        }
        // ---- load B tile into Bs[kk][col] ----
        if (TB == 0) {
            int kk = tid >> 5;
            int c4 = (tid & 31) * 4;
            float4 v = *(const float4*)&B[(size_t)(k0 + kk) * ldb + jb + c4];
            *(float4*)&Bs[kk][c4] = v;
        } else {
            int col  = tid >> 1;
            int kofs = (tid & 1) * 4;
            float4 v = *(const float4*)&B[(size_t)(jb + col) * ldb + k0 + kofs];
            Bs[kofs + 0][col] = v.x;
            Bs[kofs + 1][col] = v.y;
            Bs[kofs + 2][col] = v.z;
            Bs[kofs + 3][col] = v.w;
        }
        __syncthreads();

        #pragma unroll
        for (int kk = 0; kk < 8; kk++) {
            float a[8], b[8];
            *(float4*)&a[0] = *(float4*)&As[kk][r0];
            *(float4*)&a[4] = *(float4*)&As[kk][r0 + 4];
            *(float4*)&b[0] = *(float4*)&Bs[kk][c0];
            *(float4*)&b[4] = *(float4*)&Bs[kk][c0 + 4];
            #pragma unroll
            for (int r = 0; r < 8; r++)
                #pragma unroll
                for (int c = 0; c < 8; c++)
                    acc[r][c] = fmaf(a[r], b[c], acc[r][c]);
        }
        __syncthreads();
    }

    #pragma unroll
    for (int r = 0; r < 8; r++) {
        int i = ib + r0 + r;
        #pragma unroll
        for (int c = 0; c < 8; c++) {
            int j = jb + c0 + c;
            float v = alpha * acc[r][c];
            if (MASK) v = (j - i > APER) ? v : -FMAXV;
            C[(size_t)i * ldc + j] = v;
        }
    }
}

// Row softmax over n=4096 columns, one block (256 threads) per row, in-place.
// -FMAX masked entries -> exp(-huge)=0; fully-masked rows -> uniform 1/n,
// both matching the reference exactly.
__global__ void __launch_bounds__(256)
softmax_kernel(float* __restrict__ att, int n)
{
    const int row = blockIdx.x;
    const int tid = threadIdx.x;
    float* p = att + (size_t)row * n;

    float4 v[4];
    float mx = -FMAXV;
    #pragma unroll
    for (int i = 0; i < 4; i++) {
        v[i] = *(const float4*)&p[(tid + i * 256) * 4];
        mx = fmaxf(mx, fmaxf(fmaxf(v[i].x, v[i].y), fmaxf(v[i].z, v[i].w)));
    }
    // block max
    #pragma unroll
    for (int o = 16; o > 0; o >>= 1)
        mx = fmaxf(mx, __shfl_xor_sync(0xffffffffu, mx, o));
    __shared__ float red[8];
    if ((tid & 31) == 0) red[tid >> 5] = mx;
    __syncthreads();
    mx = red[0];
    #pragma unroll
    for (int w = 1; w < 8; w++) mx = fmaxf(mx, red[w]);
    __syncthreads();

    float s = 0.f;
    #pragma unroll
    for (int i = 0; i < 4; i++) {
        v[i].x = expf(v[i].x - mx); s += v[i].x;
        v[i].y = expf(v[i].y - mx); s += v[i].y;
        v[i].z = expf(v[i].z - mx); s += v[i].z;
        v[i].w = expf(v[i].w - mx); s += v[i].w;
    }
    #pragma unroll
    for (int o = 16; o > 0; o >>= 1)
        s += __shfl_xor_sync(0xffffffffu, s, o);
    if ((tid & 31) == 0) red[tid >> 5] = s;
    __syncthreads();
    s = red[0];
    #pragma unroll
    for (int w = 1; w < 8; w++) s += red[w];

    float inv = 1.0f / s;
    #pragma unroll
    for (int i = 0; i < 4; i++) {
        v[i].x *= inv; v[i].y *= inv; v[i].z *= inv; v[i].w *= inv;
        *(float4*)&p[(tid + i * 256) * 4] = v[i];
    }
}

extern "C" void kernel_launch(void* const* d_in, const int* in_sizes, int n_in,
                              void* d_out, int out_size)
{
    const float* x    = (const float*)d_in[0];
    const float* WK   = (const float*)d_in[1];
    const float* WQ   = (const float*)d_in[2];
    const float* WV   = (const float*)d_in[3];
    const float* Wout = (const float*)d_in[4];

    const int m = 1024, d = 1024;
    const int n = in_sizes[0] / m;   // 4096

    float* out   = (float*)d_out;
    float* y_out = out;                       // [n, m]
    float* att   = out + (size_t)n * m;       // [n, n]

    float *gK, *gQ, *gV, *gY;
    cudaGetSymbolAddress((void**)&gK, g_K);
    cudaGetSymbolAddress((void**)&gQ, g_Q);
    cudaGetSymbolAddress((void**)&gV, g_V);
    cudaGetSymbolAddress((void**)&gY, g_Y);

    dim3 th(256);

    // K = x@WK, Q = 0.06*(x@WQ), V = x@WV   [n,m]x[m,d]
    dim3 g1(d / 128, n / 128);
    sgemm_kernel<0, 0, false><<<g1, th>>>(x, WK, gK, n, d, m, m, d, d, 1.0f);
    sgemm_kernel<0, 0, false><<<g1, th>>>(x, WQ, gQ, n, d, m, m, d, d, 0.06f);
    sgemm_kernel<0, 0, false><<<g1, th>>>(x, WV, gV, n, d, m, m, d, d, 1.0f);

    // logits = Q @ K^T with aperture mask, written into att region of d_out
    dim3 g2(n / 128, n / 128);
    sgemm_kernel<0, 1, true><<<g2, th>>>(gQ, gK, att, n, n, d, d, d, n, 1.0f);

    // softmax rows, in place
    softmax_kernel<<<n, th>>>(att, n);

    // y = att^T @ V   (faithful transpose quirk): C[i,k] = sum_j att[j,i]*V[j,k]
    dim3 g3(d / 128, n / 128);
    sgemm_kernel<1, 0, false><<<g3, th>>>(att, gV, gY, n, d, n, n, d, d, 1.0f);

    // y_out = gY @ Wout   [n,d]x[d,m]
    dim3 g4(m / 128, n / 128);
    sgemm_kernel<0, 0, false><<<g4, th>>>(gY, Wout, y_out, n, m, d, d, m, m, 1.0f);
}

// round 3
// speedup vs baseline: 2.2200x; 2.2200x over previous
#include <cuda_runtime.h>
#include <stdint.h>

#define FMAXV 3.4028235e38f

// ============================================================
// Device scratch (allocation-free). Split buffers: [2][rows][K]
// plane 0 = tf32-hi, plane 1 = tf32(residual)
// ============================================================
__device__ float g_xS  [2ull*4096*1024];
__device__ float g_WKt [2ull*1024*1024];
__device__ float g_WQt [2ull*1024*1024];
__device__ float g_WVt [2ull*1024*1024];
__device__ float g_Wot [2ull*1024*1024];
__device__ float g_KS  [2ull*4096*1024];
__device__ float g_QS  [2ull*4096*1024];
__device__ float g_V   [4096ull*1024];
__device__ float g_VtS [2ull*1024*4096];
__device__ float g_attT[2ull*4096*4096];
__device__ float g_YS  [2ull*4096*1024];

// ============================================================
// Helpers (base sm_103-safe: mma.sync tf32 + cp.async only)
// ============================================================
__device__ __forceinline__ float tf32_rn(float a) {
    uint32_t u; asm("cvt.rna.tf32.f32 %0, %1;" : "=r"(u) : "f"(a));
    return __uint_as_float(u);
}
__device__ __forceinline__ uint32_t smem_u32(const void* p) {
    uint32_t a;
    asm("{ .reg .u64 t; cvta.to.shared.u64 t, %1; cvt.u32.u64 %0, t; }" : "=r"(a) : "l"(p));
    return a;
}
__device__ __forceinline__ void cp16(float* s, const float* g) {
    uint32_t a = smem_u32(s);
    asm volatile("cp.async.cg.shared.global [%0], [%1], 16;" :: "r"(a), "l"(g));
}
#define CP_COMMIT()  asm volatile("cp.async.commit_group;" ::: "memory")
#define CP_WAIT(N)   asm volatile("cp.async.wait_group %0;" :: "n"(N) : "memory")

__device__ __forceinline__ void mma8(float* c, const uint32_t* a, const uint32_t* b) {
    asm volatile(
        "mma.sync.aligned.m16n8k8.row.col.f32.tf32.tf32.f32 "
        "{%0,%1,%2,%3}, {%4,%5,%6,%7}, {%8,%9}, {%0,%1,%2,%3};"
        : "+f"(c[0]), "+f"(c[1]), "+f"(c[2]), "+f"(c[3])
        : "r"(a[0]), "r"(a[1]), "r"(a[2]), "r"(a[3]), "r"(b[0]), "r"(b[1]));
}

// ============================================================
// GEMM: D[m,n] = sum_k A[m,k]*B[n,k], A/B pre-split hi/lo (3xTF32).
// Tile 128x128, BK=16, 256 thr (8 warps of 64x32), double-buffer cp.async.
// SMEM row stride 20 floats -> conflict-free mma fragment loads.
// EPI: 0 = write split hi/lo (alpha applied), 1 = fp32, 2 = fp32 + aperture mask
// SKIP: 1 = fully-masked tile fast path; 2 = attT K-chunk range skip
// ============================================================
#define SROW 20
#define BUF_F (128 * SROW)            // floats per operand buffer (2560)
#define STAGE_F (4 * BUF_F)           // Ah, Al, Bh, Bl (10240 floats = 40960 B)
#define SMEM_DYN (2 * STAGE_F * 4)    // 81920 B

template <int EPI, int SKIP>
__global__ void __launch_bounds__(256, 2)
gemm_mma(const float* __restrict__ A, const float* __restrict__ B,
         float* __restrict__ C, int lda, int ldb, int ldc,
         long long planeA, long long planeB, long long planeC,
         int nch, float alpha)
{
    const int tid = threadIdx.x;
    const int IB = blockIdx.y * 128;
    const int JB = blockIdx.x * 128;

    if (SKIP == 1 && (JB + 127 - IB) <= 256) {
        // whole tile masked: write -FMAX, no MMA
        int row = tid >> 1, half = (tid & 1) * 64;
        float4 mv = make_float4(-FMAXV, -FMAXV, -FMAXV, -FMAXV);
        float* p = C + (size_t)(IB + row) * ldc + JB + half;
        #pragma unroll
        for (int gq = 0; gq < 16; gq++) ((float4*)p)[gq] = mv;
        return;
    }

    extern __shared__ float sm[];

    // K-chunk schedule: chunks [0,e1) U [s2,nch)
    int e1 = nch, s2 = nch;
    if (SKIP == 2) {
        int n1 = IB - 129; if (n1 < 0) n1 = 0;   // att col nonzero only for j < IB-129
        e1 = (n1 + 15) >> 4; if (e1 > nch) e1 = nch;
        s2 = 239; if (s2 < e1) s2 = e1;          // ... or j >= 3839 (uniform rows)
    }
    const int T = e1 + (nch - s2);

    const int lane = tid & 31, w = tid >> 5;
    const int g = lane >> 2, tig = lane & 3;
    const int RW = (w >> 2) * 64, CW = (w & 3) * 32;

    auto issue = [&](int t) {
        int s = t & 1;
        int ch = (t < e1) ? t : (s2 + t - e1);
        int k0 = ch * 16;
        float* sb = sm + s * STAGE_F;
        #pragma unroll
        for (int r = 0; r < 2; r++) {
            int c = tid + r * 256;
            int row = c >> 2, kc = (c & 3) * 4;
            const float* gA = A + (size_t)(IB + row) * lda + k0 + kc;
            const float* gB = B + (size_t)(JB + row) * ldb + k0 + kc;
            float* sA = sb + row * SROW + kc;
            float* sB = sb + 2 * BUF_F + row * SROW + kc;
            cp16(sA, gA);            cp16(sA + BUF_F, gA + planeA);
            cp16(sB, gB);            cp16(sB + BUF_F, gB + planeB);
        }
        CP_COMMIT();
    };

    float acc[64];
    #pragma unroll
    for (int i = 0; i < 64; i++) acc[i] = 0.f;

    issue(0);
    if (T > 1) issue(1);

    for (int t = 0; t < T; t++) {
        if (t + 1 < T) { CP_WAIT(1); } else { CP_WAIT(0); }
        __syncthreads();

        const float* sb  = sm + (t & 1) * STAGE_F;
        const float* sAh = sb;
        const float* sAl = sb + BUF_F;
        const float* sBh = sb + 2 * BUF_F;
        const float* sBl = sb + 3 * BUF_F;

        #pragma unroll
        for (int ks = 0; ks < 2; ks++) {
            const int kc = ks * 8 + tig;
            uint32_t af[16], bf[8];
            // load A-hi fragments
            #pragma unroll
            for (int mt = 0; mt < 4; mt++) {
                const float* p = sAh + (RW + mt * 16 + g) * SROW + kc;
                af[mt*4+0] = __float_as_uint(p[0]);
                af[mt*4+1] = __float_as_uint(p[8 * SROW]);
                af[mt*4+2] = __float_as_uint(p[4]);
                af[mt*4+3] = __float_as_uint(p[8 * SROW + 4]);
            }
            // pass 1: Ah * Bl
            #pragma unroll
            for (int nt = 0; nt < 4; nt++) {
                const float* p = sBl + (CW + nt * 8 + g) * SROW + kc;
                bf[nt*2+0] = __float_as_uint(p[0]);
                bf[nt*2+1] = __float_as_uint(p[4]);
            }
            #pragma unroll
            for (int mt = 0; mt < 4; mt++)
                #pragma unroll
                for (int nt = 0; nt < 4; nt++)
                    mma8(&acc[(mt*4+nt)*4], &af[mt*4], &bf[nt*2]);
            // pass 2: Ah * Bh
            #pragma unroll
            for (int nt = 0; nt < 4; nt++) {
                const float* p = sBh + (CW + nt * 8 + g) * SROW + kc;
                bf[nt*2+0] = __float_as_uint(p[0]);
                bf[nt*2+1] = __float_as_uint(p[4]);
            }
            #pragma unroll
            for (int mt = 0; mt < 4; mt++)
                #pragma unroll
                for (int nt = 0; nt < 4; nt++)
                    mma8(&acc[(mt*4+nt)*4], &af[mt*4], &bf[nt*2]);
            // pass 3: Al * Bh
            #pragma unroll
            for (int mt = 0; mt < 4; mt++) {
                const float* p = sAl + (RW + mt * 16 + g) * SROW + kc;
                af[mt*4+0] = __float_as_uint(p[0]);
                af[mt*4+1] = __float_as_uint(p[8 * SROW]);
                af[mt*4+2] = __float_as_uint(p[4]);
                af[mt*4+3] = __float_as_uint(p[8 * SROW + 4]);
            }
            #pragma unroll
            for (int mt = 0; mt < 4; mt++)
                #pragma unroll
                for (int nt = 0; nt < 4; nt++)
                    mma8(&acc[(mt*4+nt)*4], &af[mt*4], &bf[nt*2]);
        }
        __syncthreads();
        if (t + 2 < T) issue(t + 2);
    }

    // ---------------- epilogue ----------------
    #pragma unroll
    for (int mt = 0; mt < 4; mt++) {
        #pragma unroll
        for (int nt = 0; nt < 4; nt++) {
            const float* cc = &acc[(mt*4+nt)*4];
            int r0 = IB + RW + mt * 16 + g;
            int c0 = JB + CW + nt * 8 + 2 * tig;
            #pragma unroll
            for (int half = 0; half < 2; half++) {
                int r = r0 + half * 8;
                float v0 = cc[half * 2 + 0] * alpha;
                float v1 = cc[half * 2 + 1] * alpha;
                float* dst = C + (size_t)r * ldc + c0;
                if (EPI == 2) {
                    v0 = (c0 + 0 - r > 256) ? v0 : -FMAXV;
                    v1 = (c0 + 1 - r > 256) ? v1 : -FMAXV;
                    *(float2*)dst = make_float2(v0, v1);
                } else if (EPI == 1) {
                    *(float2*)dst = make_float2(v0, v1);
                } else {
                    float h0 = tf32_rn(v0), l0 = tf32_rn(v0 - h0);
                    float h1 = tf32_rn(v1), l1 = tf32_rn(v1 - h1);
                    *(float2*)dst            = make_float2(h0, h1);
                    *(float2*)(dst + planeC) = make_float2(l0, l1);
                }
            }
        }
    }
}

// ============================================================
// Elementwise split: out[2][S]
// ============================================================
__global__ void split_kernel(const float* __restrict__ in, float* __restrict__ out, size_t S)
{
    size_t i = (size_t)blockIdx.x * blockDim.x + threadIdx.x;
    size_t stride = (size_t)gridDim.x * blockDim.x;
    for (; i < S; i += stride) {
        float v = in[i];
        float h = tf32_rn(v);
        out[i] = h;
        out[S + i] = tf32_rn(v - h);
    }
}

// Transpose + split: in[R][C] -> out[2][C][R]
__global__ void transpose_split(const float* __restrict__ in, float* __restrict__ out,
                                int R, int C)
{
    __shared__ float t[32][33];
    int c0 = blockIdx.x * 32, r0 = blockIdx.y * 32;
    int tx = threadIdx.x, ty = threadIdx.y;
    #pragma unroll
    for (int i = 0; i < 32; i += 8)
        t[ty + i][tx] = in[(size_t)(r0 + ty + i) * C + c0 + tx];
    __syncthreads();
    size_t plane = (size_t)R * C;
    #pragma unroll
    for (int i = 0; i < 32; i += 8) {
        float v = t[tx][ty + i];
        float h = tf32_rn(v), l = tf32_rn(v - h);
        size_t o = (size_t)(c0 + ty + i) * R + r0 + tx;
        out[o] = h;
        out[plane + o] = l;
    }
}

// ============================================================
// Row softmax over n=4096, one block (256 threads) per row, in-place.
// ============================================================
__global__ void __launch_bounds__(256)
softmax_kernel(float* __restrict__ att, int n)
{
    const int row = blockIdx.x;
    const int tid = threadIdx.x;
    float* p = att + (size_t)row * n;

    float4 v[4];
    float mx = -FMAXV;
    #pragma unroll
    for (int i = 0; i < 4; i++) {
        v[i] = *(const float4*)&p[(tid + i * 256) * 4];
        mx = fmaxf(mx, fmaxf(fmaxf(v[i].x, v[i].y), fmaxf(v[i].z, v[i].w)));
    }
    #pragma unroll
    for (int o = 16; o > 0; o >>= 1) mx = fmaxf(mx, __shfl_xor_sync(0xffffffffu, mx, o));
    __shared__ float red[8];
    if ((tid & 31) == 0) red[tid >> 5] = mx;
    __syncthreads();
    mx = red[0];
    #pragma unroll
    for (int ww = 1; ww < 8; ww++) mx = fmaxf(mx, red[ww]);
    __syncthreads();

    float s = 0.f;
    #pragma unroll
    for (int i = 0; i < 4; i++) {
        v[i].x = expf(v[i].x - mx); s += v[i].x;
        v[i].y = expf(v[i].y - mx); s += v[i].y;
        v[i].z = expf(v[i].z - mx); s += v[i].z;
        v[i].w = expf(v[i].w - mx); s += v[i].w;
    }
    #pragma unroll
    for (int o = 16; o > 0; o >>= 1) s += __shfl_xor_sync(0xffffffffu, s, o);
    if ((tid & 31) == 0) red[tid >> 5] = s;
    __syncthreads();
    s = red[0];
    #pragma unroll
    for (int ww = 1; ww < 8; ww++) s += red[ww];

    float inv = 1.0f / s;
    #pragma unroll
    for (int i = 0; i < 4; i++) {
        v[i].x *= inv; v[i].y *= inv; v[i].z *= inv; v[i].w *= inv;
        *(float4*)&p[(tid + i * 256) * 4] = v[i];
    }
}

// ============================================================
// Host
// ============================================================
extern "C" void kernel_launch(void* const* d_in, const int* in_sizes, int n_in,
                              void* d_out, int out_size)
{
    const float* x    = (const float*)d_in[0];
    const float* WK   = (const float*)d_in[1];
    const float* WQ   = (const float*)d_in[2];
    const float* WV   = (const float*)d_in[3];
    const float* Wout = (const float*)d_in[4];

    const int m = 1024;
    const int n = in_sizes[0] / m;   // 4096

    float* y_out = (float*)d_out;                 // [n, m]
    float* att   = y_out + (size_t)n * m;         // [n, n]

    float *pxS, *pWKt, *pWQt, *pWVt, *pWot, *pKS, *pQS, *pV, *pVt, *pattT, *pYS;
    cudaGetSymbolAddress((void**)&pxS,  g_xS);
    cudaGetSymbolAddress((void**)&pWKt, g_WKt);
    cudaGetSymbolAddress((void**)&pWQt, g_WQt);
    cudaGetSymbolAddress((void**)&pWVt, g_WVt);
    cudaGetSymbolAddress((void**)&pWot, g_Wot);
    cudaGetSymbolAddress((void**)&pKS,  g_KS);
    cudaGetSymbolAddress((void**)&pQS,  g_QS);
    cudaGetSymbolAddress((void**)&pV,   g_V);
    cudaGetSymbolAddress((void**)&pVt,  g_VtS);
    cudaGetSymbolAddress((void**)&pattT, g_attT);
    cudaGetSymbolAddress((void**)&pYS,  g_YS);

    cudaFuncSetAttribute(gemm_mma<0, 0>, cudaFuncAttributeMaxDynamicSharedMemorySize, SMEM_DYN);
    cudaFuncSetAttribute(gemm_mma<1, 0>, cudaFuncAttributeMaxDynamicSharedMemorySize, SMEM_DYN);
    cudaFuncSetAttribute(gemm_mma<2, 1>, cudaFuncAttributeMaxDynamicSharedMemorySize, SMEM_DYN);
    cudaFuncSetAttribute(gemm_mma<0, 2>, cudaFuncAttributeMaxDynamicSharedMemorySize, SMEM_DYN);

    dim3 tb32(32, 8);
    const long long PX = 4096LL * 1024;  // x/K/Q/Y/Vt-sized plane
    const long long PW = 1024LL * 1024;  // weight plane
    const long long PA = 4096LL * 4096;  // attT plane

    // Split x; transpose+split all weights
    split_kernel<<<4096, 256>>>(x, pxS, (size_t)n * m);
    transpose_split<<<dim3(32, 32), tb32>>>(WK,   pWKt, 1024, 1024);
    transpose_split<<<dim3(32, 32), tb32>>>(WQ,   pWQt, 1024, 1024);
    transpose_split<<<dim3(32, 32), tb32>>>(WV,   pWVt, 1024, 1024);
    transpose_split<<<dim3(32, 32), tb32>>>(Wout, pWot, 1024, 1024);

    // K = x@WK (split out), Q = 0.06*(x@WQ) (split out), V = x@WV (fp32)
    dim3 g1(8, 32);
    gemm_mma<0, 0><<<g1, 256, SMEM_DYN>>>(pxS, pWKt, pKS, 1024, 1024, 1024, PX, PW, PX, 64, 1.0f);
    gemm_mma<0, 0><<<g1, 256, SMEM_DYN>>>(pxS, pWQt, pQS, 1024, 1024, 1024, PX, PW, PX, 64, 0.06f);
    gemm_mma<1, 0><<<g1, 256, SMEM_DYN>>>(pxS, pWVt, pV,  1024, 1024, 1024, PX, PW, 0,  64, 1.0f);

    // logits = Q@K^T with aperture mask -> att (fp32, in d_out)
    gemm_mma<2, 1><<<dim3(32, 32), 256, SMEM_DYN>>>(pQS, pKS, att, 1024, 1024, 4096, PX, PX, 0, 64, 1.0f);

    softmax_kernel<<<n, 256>>>(att, n);

    // attT[i][j] = att[j][i] (split); Vt[l][j] = V[j][l] (split)
    transpose_split<<<dim3(128, 128), tb32>>>(att, pattT, 4096, 4096);
    transpose_split<<<dim3(32, 128),  tb32>>>(pV,  pVt,   4096, 1024);

    // Y = att^T @ V (split out), K-chunk skip on zero att columns
    gemm_mma<0, 2><<<dim3(8, 32), 256, SMEM_DYN>>>(pattT, pVt, pYS, 4096, 4096, 1024, PA, PX, PX, 256, 1.0f);

    // y_out = Y @ Wout (fp32)
    gemm_mma<1, 0><<<dim3(8, 32), 256, SMEM_DYN>>>(pYS, pWot, y_out, 1024, 1024, 1024, PX, PW, 0, 64, 1.0f);
}

// round 4
// speedup vs baseline: 3.6997x; 1.6665x over previous
#include <cuda_runtime.h>
#include <cuda_bf16.h>
#include <stdint.h>

#define FMAXV 3.4028235e38f

// ============================================================
// Device scratch (allocation-free). Split buffers: [2][rows][K] bf16
// plane 0 = bf16-hi, plane 1 = bf16(residual)
// ============================================================
__device__ __nv_bfloat16 g_xS  [2ull*4096*1024];
__device__ __nv_bfloat16 g_WKt [2ull*1024*1024];
__device__ __nv_bfloat16 g_WQt [2ull*1024*1024];
__device__ __nv_bfloat16 g_WVt [2ull*1024*1024];
__device__ __nv_bfloat16 g_Wot [2ull*1024*1024];
__device__ __nv_bfloat16 g_KS  [2ull*4096*1024];
__device__ __nv_bfloat16 g_QS  [2ull*4096*1024];
__device__ float         g_V   [4096ull*1024];
__device__ __nv_bfloat16 g_VtS [2ull*1024*4096];
__device__ __nv_bfloat16 g_attT[2ull*4096*4096];
__device__ __nv_bfloat16 g_YS  [2ull*4096*1024];

// ============================================================
// Helpers (base sm_103-safe: mma.sync bf16 + cp.async only)
// ============================================================
__device__ __forceinline__ uint32_t smem_u32(const void* p) {
    uint32_t a;
    asm("{ .reg .u64 t; cvta.to.shared.u64 t, %1; cvt.u32.u64 %0, t; }" : "=r"(a) : "l"(p));
    return a;
}
__device__ __forceinline__ void cp16(void* s, const void* g) {
    uint32_t a = smem_u32(s);
    asm volatile("cp.async.cg.shared.global [%0], [%1], 16;" :: "r"(a), "l"(g));
}
#define CP_COMMIT()  asm volatile("cp.async.commit_group;" ::: "memory")
#define CP_WAIT(N)   asm volatile("cp.async.wait_group %0;" :: "n"(N) : "memory")

__device__ __forceinline__ void mma16(float* c, const uint32_t* a, const uint32_t* b) {
    asm volatile(
        "mma.sync.aligned.m16n8k16.row.col.f32.bf16.bf16.f32 "
        "{%0,%1,%2,%3}, {%4,%5,%6,%7}, {%8,%9}, {%0,%1,%2,%3};"
        : "+f"(c[0]), "+f"(c[1]), "+f"(c[2]), "+f"(c[3])
        : "r"(a[0]), "r"(a[1]), "r"(a[2]), "r"(a[3]), "r"(b[0]), "r"(b[1]));
}
__device__ __forceinline__ uint32_t pack_bf16x2_split(float v, float* mid) {
    __nv_bfloat16 h = __float2bfloat16_rn(v);
    *mid = v - __bfloat162float(h);
    return (uint32_t)__bfloat16_as_ushort(h);
}

// ============================================================
// GEMM: D[m,n] = sum_k A[m,k]*B[n,k]; A,B = 2-plane bf16 split.
// 3 products per K16: Ah*Bh + Ah*Bm + Am*Bh (mma m16n8k16 bf16).
// Tile 128x128, BK=16, 256 thr (8 warps, 64x32 warp tiles), 3-stage cp.async.
// SMEM row stride 24 halves -> conflict-free 32-bit fragment loads.
// EPI: 0 = write bf16 split hi/mid (alpha applied), 1 = fp32, 2 = fp32 + mask
// SKIP: 1 = fully-masked tile fast path; 2 = attT K-chunk range skip
// ============================================================
#define SROWH 24
#define BUF_H (128 * SROWH)           // 3072 halves per plane buffer
#define STAGE_H (4 * BUF_H)           // Ah, Am, Bh, Bm
#define NSTAGE 3
#define SMEM_DYN (NSTAGE * STAGE_H * 2)   // 73728 bytes

template <int EPI, int SKIP>
__global__ void __launch_bounds__(256, 2)
gemm_bf16(const __nv_bfloat16* __restrict__ A, const __nv_bfloat16* __restrict__ B,
          void* __restrict__ Cv, int lda, int ldb, int ldc,
          long long planeA, long long planeB, long long planeC,
          int nch, float alpha)
{
    const int tid = threadIdx.x;
    const int IB = blockIdx.y * 128;
    const int JB = blockIdx.x * 128;

    if (SKIP == 1 && (JB + 127 - IB) <= 256) {
        // whole tile masked: write -FMAX, no MMA
        float* Cf = (float*)Cv;
        int row = tid >> 1, half = (tid & 1) * 64;
        float4 mv = make_float4(-FMAXV, -FMAXV, -FMAXV, -FMAXV);
        float* p = Cf + (size_t)(IB + row) * ldc + JB + half;
        #pragma unroll
        for (int gq = 0; gq < 16; gq++) ((float4*)p)[gq] = mv;
        return;
    }

    extern __shared__ __nv_bfloat16 smh[];

    // K-chunk schedule: chunks [0,e1) U [s2,nch)
    int e1 = nch, s2 = nch;
    if (SKIP == 2) {
        int n1 = IB - 129; if (n1 < 0) n1 = 0;   // att col nonzero only for j < IB-129
        e1 = (n1 + 15) >> 4; if (e1 > nch) e1 = nch;
        s2 = 239; if (s2 < e1) s2 = e1;          // ... or j >= 3839 (uniform rows)
    }
    const int T = e1 + (nch - s2);

    const int lane = tid & 31, w = tid >> 5;
    const int g = lane >> 2, tg = lane & 3;
    const int RW = (w >> 2) * 64, CW = (w & 3) * 32;

    auto issue = [&](int t) {
        int s = t % NSTAGE;
        int ch = (t < e1) ? t : (s2 + t - e1);
        int k0 = ch * 16;
        __nv_bfloat16* sb = smh + s * STAGE_H;
        #pragma unroll
        for (int r = 0; r < 4; r++) {
            int c = tid + r * 256;          // 0..1023
            int op = c >> 9;                 // 0=A, 1=B
            int rem = c & 511;
            int pl = rem >> 8;               // plane
            int rr = (rem & 255) >> 1;       // row 0..127
            int ck = rem & 1;                // 8-half chunk
            const __nv_bfloat16* src = (op ? B : A)
                + (size_t)pl * (op ? planeB : planeA)
                + (size_t)((op ? JB : IB) + rr) * (op ? ldb : lda) + k0 + ck * 8;
            __nv_bfloat16* dst = sb + op * 2 * BUF_H + pl * BUF_H + rr * SROWH + ck * 8;
            cp16(dst, src);
        }
        CP_COMMIT();
    };

    float acc[64];
    #pragma unroll
    for (int i = 0; i < 64; i++) acc[i] = 0.f;

    issue(0);
    if (T > 1) issue(1);
    if (T > 2) issue(2);

    for (int t = 0; t < T; t++) {
        if (t + 2 < T) { CP_WAIT(2); } else if (t + 1 < T) { CP_WAIT(1); } else { CP_WAIT(0); }
        __syncthreads();

        const __nv_bfloat16* sb  = smh + (t % NSTAGE) * STAGE_H;
        const __nv_bfloat16* sAh = sb;
        const __nv_bfloat16* sAm = sb + BUF_H;
        const __nv_bfloat16* sBh = sb + 2 * BUF_H;
        const __nv_bfloat16* sBm = sb + 3 * BUF_H;

        uint32_t af[16], bh[8], bm[8];
        // A-hi fragments (k16)
        #pragma unroll
        for (int mt = 0; mt < 4; mt++) {
            const __nv_bfloat16* p = sAh + (RW + mt * 16 + g) * SROWH + 2 * tg;
            af[mt*4+0] = *(const uint32_t*)(p);
            af[mt*4+1] = *(const uint32_t*)(p + 8 * SROWH);
            af[mt*4+2] = *(const uint32_t*)(p + 8);
            af[mt*4+3] = *(const uint32_t*)(p + 8 * SROWH + 8);
        }
        #pragma unroll
        for (int nt = 0; nt < 4; nt++) {
            const __nv_bfloat16* p = sBh + (CW + nt * 8 + g) * SROWH + 2 * tg;
            bh[nt*2+0] = *(const uint32_t*)(p);
            bh[nt*2+1] = *(const uint32_t*)(p + 8);
        }
        // pass 1: Ah * Bh
        #pragma unroll
        for (int mt = 0; mt < 4; mt++)
            #pragma unroll
            for (int nt = 0; nt < 4; nt++)
                mma16(&acc[(mt*4+nt)*4], &af[mt*4], &bh[nt*2]);
        // pass 2: Ah * Bm
        #pragma unroll
        for (int nt = 0; nt < 4; nt++) {
            const __nv_bfloat16* p = sBm + (CW + nt * 8 + g) * SROWH + 2 * tg;
            bm[nt*2+0] = *(const uint32_t*)(p);
            bm[nt*2+1] = *(const uint32_t*)(p + 8);
        }
        #pragma unroll
        for (int mt = 0; mt < 4; mt++)
            #pragma unroll
            for (int nt = 0; nt < 4; nt++)
                mma16(&acc[(mt*4+nt)*4], &af[mt*4], &bm[nt*2]);
        // pass 3: Am * Bh
        #pragma unroll
        for (int mt = 0; mt < 4; mt++) {
            const __nv_bfloat16* p = sAm + (RW + mt * 16 + g) * SROWH + 2 * tg;
            af[mt*4+0] = *(const uint32_t*)(p);
            af[mt*4+1] = *(const uint32_t*)(p + 8 * SROWH);
            af[mt*4+2] = *(const uint32_t*)(p + 8);
            af[mt*4+3] = *(const uint32_t*)(p + 8 * SROWH + 8);
        }
        #pragma unroll
        for (int mt = 0; mt < 4; mt++)
            #pragma unroll
            for (int nt = 0; nt < 4; nt++)
                mma16(&acc[(mt*4+nt)*4], &af[mt*4], &bh[nt*2]);

        __syncthreads();
        if (t + 3 < T) issue(t + 3);
    }

    // ---------------- epilogue ----------------
    #pragma unroll
    for (int mt = 0; mt < 4; mt++) {
        #pragma unroll
        for (int nt = 0; nt < 4; nt++) {
            const float* cc = &acc[(mt*4+nt)*4];
            int r0 = IB + RW + mt * 16 + g;
            int c0 = JB + CW + nt * 8 + 2 * tg;
            #pragma unroll
            for (int half = 0; half < 2; half++) {
                int r = r0 + half * 8;
                float v0 = cc[half * 2 + 0] * alpha;
                float v1 = cc[half * 2 + 1] * alpha;
                if (EPI == 2) {
                    float* dst = (float*)Cv + (size_t)r * ldc + c0;
                    v0 = (c0 + 0 - r > 256) ? v0 : -FMAXV;
                    v1 = (c0 + 1 - r > 256) ? v1 : -FMAXV;
                    *(float2*)dst = make_float2(v0, v1);
                } else if (EPI == 1) {
                    float* dst = (float*)Cv + (size_t)r * ldc + c0;
                    *(float2*)dst = make_float2(v0, v1);
                } else {
                    __nv_bfloat16* dst = (__nv_bfloat16*)Cv + (size_t)r * ldc + c0;
                    float m0, m1;
                    uint32_t h0 = pack_bf16x2_split(v0, &m0);
                    uint32_t h1 = pack_bf16x2_split(v1, &m1);
                    uint32_t lo0 = (uint32_t)__bfloat16_as_ushort(__float2bfloat16_rn(m0));
                    uint32_t lo1 = (uint32_t)__bfloat16_as_ushort(__float2bfloat16_rn(m1));
                    *(uint32_t*)dst            = h0 | (h1 << 16);
                    *(uint32_t*)(dst + planeC) = lo0 | (lo1 << 16);
                }
            }
        }
    }
}

// ============================================================
// Elementwise split to 2 bf16 planes: out[2][S]
// ============================================================
__global__ void split_kernel(const float* __restrict__ in, __nv_bfloat16* __restrict__ out,
                             size_t S)
{
    size_t i = (size_t)blockIdx.x * blockDim.x + threadIdx.x;
    size_t stride = (size_t)gridDim.x * blockDim.x;
    for (; i < S; i += stride) {
        float v = in[i];
        __nv_bfloat16 h = __float2bfloat16_rn(v);
        out[i] = h;
        out[S + i] = __float2bfloat16_rn(v - __bfloat162float(h));
    }
}

// Transpose + split: in[R][C] fp32 -> out[2][C][R] bf16
__global__ void transpose_split(const float* __restrict__ in, __nv_bfloat16* __restrict__ out,
                                int R, int C)
{
    __shared__ float t[32][33];
    int c0 = blockIdx.x * 32, r0 = blockIdx.y * 32;
    int tx = threadIdx.x, ty = threadIdx.y;
    #pragma unroll
    for (int i = 0; i < 32; i += 8)
        t[ty + i][tx] = in[(size_t)(r0 + ty + i) * C + c0 + tx];
    __syncthreads();
    size_t plane = (size_t)R * C;
    #pragma unroll
    for (int i = 0; i < 32; i += 8) {
        float v = t[tx][ty + i];
        __nv_bfloat16 h = __float2bfloat16_rn(v);
        __nv_bfloat16 l = __float2bfloat16_rn(v - __bfloat162float(h));
        size_t o = (size_t)(c0 + ty + i) * R + r0 + tx;
        out[o] = h;
        out[plane + o] = l;
    }
}

// ============================================================
// Row softmax over n=4096, one block (256 threads) per row, in-place.
// ============================================================
__global__ void __launch_bounds__(256)
softmax_kernel(float* __restrict__ att, int n)
{
    const int row = blockIdx.x;
    const int tid = threadIdx.x;
    float* p = att + (size_t)row * n;

    float4 v[4];
    float mx = -FMAXV;
    #pragma unroll
    for (int i = 0; i < 4; i++) {
        v[i] = *(const float4*)&p[(tid + i * 256) * 4];
        mx = fmaxf(mx, fmaxf(fmaxf(v[i].x, v[i].y), fmaxf(v[i].z, v[i].w)));
    }
    #pragma unroll
    for (int o = 16; o > 0; o >>= 1) mx = fmaxf(mx, __shfl_xor_sync(0xffffffffu, mx, o));
    __shared__ float red[8];
    if ((tid & 31) == 0) red[tid >> 5] = mx;
    __syncthreads();
    mx = red[0];
    #pragma unroll
    for (int ww = 1; ww < 8; ww++) mx = fmaxf(mx, red[ww]);
    __syncthreads();

    float s = 0.f;
    #pragma unroll
    for (int i = 0; i < 4; i++) {
        v[i].x = expf(v[i].x - mx); s += v[i].x;
        v[i].y = expf(v[i].y - mx); s += v[i].y;
        v[i].z = expf(v[i].z - mx); s += v[i].z;
        v[i].w = expf(v[i].w - mx); s += v[i].w;
    }
    #pragma unroll
    for (int o = 16; o > 0; o >>= 1) s += __shfl_xor_sync(0xffffffffu, s, o);
    if ((tid & 31) == 0) red[tid >> 5] = s;
    __syncthreads();
    s = red[0];
    #pragma unroll
    for (int ww = 1; ww < 8; ww++) s += red[ww];

    float inv = 1.0f / s;
    #pragma unroll
    for (int i = 0; i < 4; i++) {
        v[i].x *= inv; v[i].y *= inv; v[i].z *= inv; v[i].w *= inv;
        *(float4*)&p[(tid + i * 256) * 4] = v[i];
    }
}

// ============================================================
// Host
// ============================================================
extern "C" void kernel_launch(void* const* d_in, const int* in_sizes, int n_in,
                              void* d_out, int out_size)
{
    const float* x    = (const float*)d_in[0];
    const float* WK   = (const float*)d_in[1];
    const float* WQ   = (const float*)d_in[2];
    const float* WV   = (const float*)d_in[3];
    const float* Wout = (const float*)d_in[4];

    const int m = 1024;
    const int n = in_sizes[0] / m;   // 4096

    float* y_out = (float*)d_out;                 // [n, m]
    float* att   = y_out + (size_t)n * m;         // [n, n]

    __nv_bfloat16 *pxS, *pWKt, *pWQt, *pWVt, *pWot, *pKS, *pQS, *pVt, *pattT, *pYS;
    float* pV;
    cudaGetSymbolAddress((void**)&pxS,  g_xS);
    cudaGetSymbolAddress((void**)&pWKt, g_WKt);
    cudaGetSymbolAddress((void**)&pWQt, g_WQt);
    cudaGetSymbolAddress((void**)&pWVt, g_WVt);
    cudaGetSymbolAddress((void**)&pWot, g_Wot);
    cudaGetSymbolAddress((void**)&pKS,  g_KS);
    cudaGetSymbolAddress((void**)&pQS,  g_QS);
    cudaGetSymbolAddress((void**)&pV,   g_V);
    cudaGetSymbolAddress((void**)&pVt,  g_VtS);
    cudaGetSymbolAddress((void**)&pattT, g_attT);
    cudaGetSymbolAddress((void**)&pYS,  g_YS);

    cudaFuncSetAttribute(gemm_bf16<0, 0>, cudaFuncAttributeMaxDynamicSharedMemorySize, SMEM_DYN);
    cudaFuncSetAttribute(gemm_bf16<1, 0>, cudaFuncAttributeMaxDynamicSharedMemorySize, SMEM_DYN);
    cudaFuncSetAttribute(gemm_bf16<2, 1>, cudaFuncAttributeMaxDynamicSharedMemorySize, SMEM_DYN);
    cudaFuncSetAttribute(gemm_bf16<0, 2>, cudaFuncAttributeMaxDynamicSharedMemorySize, SMEM_DYN);

    dim3 tb32(32, 8);
    const long long PX = 4096LL * 1024;  // x/K/Q/Y/Vt-sized plane (elements)
    const long long PW = 1024LL * 1024;  // weight plane
    const long long PA = 4096LL * 4096;  // attT plane

    // Split x; transpose+split all weights
    split_kernel<<<4096, 256>>>(x, pxS, (size_t)n * m);
    transpose_split<<<dim3(32, 32), tb32>>>(WK,   pWKt, 1024, 1024);
    transpose_split<<<dim3(32, 32), tb32>>>(WQ,   pWQt, 1024, 1024);
    transpose_split<<<dim3(32, 32), tb32>>>(WV,   pWVt, 1024, 1024);
    transpose_split<<<dim3(32, 32), tb32>>>(Wout, pWot, 1024, 1024);

    // K = x@WK (split out), Q = 0.06*(x@WQ) (split out), V = x@WV (fp32)
    dim3 g1(8, 32);
    gemm_bf16<0, 0><<<g1, 256, SMEM_DYN>>>(pxS, pWKt, pKS, 1024, 1024, 1024, PX, PW, PX, 64, 1.0f);
    gemm_bf16<0, 0><<<g1, 256, SMEM_DYN>>>(pxS, pWQt, pQS, 1024, 1024, 1024, PX, PW, PX, 64, 0.06f);
    gemm_bf16<1, 0><<<g1, 256, SMEM_DYN>>>(pxS, pWVt, pV,  1024, 1024, 1024, PX, PW, 0,  64, 1.0f);

    // logits = Q@K^T with aperture mask -> att (fp32, in d_out)
    gemm_bf16<2, 1><<<dim3(32, 32), 256, SMEM_DYN>>>(pQS, pKS, att, 1024, 1024, 4096, PX, PX, 0, 64, 1.0f);

    softmax_kernel<<<n, 256>>>(att, n);

    // attT[i][j] = att[j][i] (bf16 split); Vt[l][j] = V[j][l] (bf16 split)
    transpose_split<<<dim3(128, 128), tb32>>>(att, pattT, 4096, 4096);
    transpose_split<<<dim3(32, 128),  tb32>>>(pV,  pVt,   4096, 1024);

    // Y = att^T @ V (split out), K-chunk skip on zero att columns
    gemm_bf16<0, 2><<<dim3(8, 32), 256, SMEM_DYN>>>(pattT, pVt, pYS, 4096, 4096, 1024, PA, PX, PX, 256, 1.0f);

    // y_out = Y @ Wout (fp32)
    gemm_bf16<1, 0><<<dim3(8, 32), 256, SMEM_DYN>>>(pYS, pWot, y_out, 1024, 1024, 1024, PX, PW, 0, 64, 1.0f);
}